// round 14
// baseline (speedup 1.0000x reference)
#include <cuda_runtime.h>
#include <cuda_fp16.h>
#include <math.h>
#include <cstdint>

// Problem constants
#define D_MODEL 1024
#define SEQ_L   4096
#define BATCH   4
#define M_TOK   (BATCH * SEQ_L)     // 16384 tokens
#define N1      (3 * D_MODEL)       // 3072
#define NSEG    128
#define SEGLEN  (SEQ_L / NSEG)      // 32
#define NSEQ    (BATCH * D_MODEL)   // 4096 scan sequences
#define LN_EPS  1e-5f

// ---------------------------------------------------------------------------
// Scratch (static device arrays, allocation-free)
// ---------------------------------------------------------------------------
__device__ __half g_u16[(size_t)M_TOK * N1];   // 96 MB: u (fp16)
__device__ float g_segA[NSEG * NSEQ];
__device__ float g_segB[NSEG * NSEQ];
__device__ float g_carry[NSEG * NSEQ];

// fp16 operands (plain fp16 A, B transposed [N,K])
__device__ __half g_A1[(size_t)M_TOK * D_MODEL];
__device__ __half g_B1t[(size_t)N1 * D_MODEL];
__device__ __half g_A2[(size_t)M_TOK * D_MODEL];
__device__ __half g_B2t[(size_t)D_MODEL * D_MODEL];

// ---------------------------------------------------------------------------
// PTX helpers (base sm_100-legal: cp.async, ldmatrix, mma.sync)
// ---------------------------------------------------------------------------
__device__ __forceinline__ uint32_t smem_u32(const void* p) {
    uint32_t a;
    asm("{ .reg .u64 t; cvta.to.shared.u64 t, %1; cvt.u32.u64 %0, t; }" : "=r"(a) : "l"(p));
    return a;
}
#define CP16(smem_addr, gptr) \
    asm volatile("cp.async.cg.shared.global [%0], [%1], 16;" :: "r"(smem_addr), "l"(gptr))
#define CP_COMMIT() asm volatile("cp.async.commit_group;" ::: "memory")
#define CP_WAITG1() asm volatile("cp.async.wait_group 1;" ::: "memory")

#define LDSM4(r0, r1, r2, r3, addr) \
    asm volatile("ldmatrix.sync.aligned.m8n8.x4.shared.b16 {%0,%1,%2,%3}, [%4];" \
                 : "=r"(r0), "=r"(r1), "=r"(r2), "=r"(r3) : "r"(addr))

__device__ __forceinline__ void mma16816(float* c, uint32_t a0, uint32_t a1,
                                         uint32_t a2, uint32_t a3,
                                         uint32_t b0, uint32_t b1) {
    asm volatile(
        "mma.sync.aligned.m16n8k16.row.col.f32.f16.f16.f32 "
        "{%0,%1,%2,%3}, {%4,%5,%6,%7}, {%8,%9}, {%0,%1,%2,%3};"
        : "+f"(c[0]), "+f"(c[1]), "+f"(c[2]), "+f"(c[3])
        : "r"(a0), "r"(a1), "r"(a2), "r"(a3), "r"(b0), "r"(b1));
}

// ---------------------------------------------------------------------------
// fp16 GEMM (R11-exact): C[M,N] = A[M,K] @ Bt[N,K]^T + bias
// CTA 128x128, BK=64, 256 threads = 8 warps of 64x32, 2-stage cp.async,
// B-fragment double-buffering across k16 steps.
// ---------------------------------------------------------------------------
#define ROW_STRIDE 144
#define TILE_SM (128 * ROW_STRIDE)              // 18432 B
#define STAGE_SM (2 * TILE_SM)                  // 36864 B (A + B)
#define GEMM_SMEM (2 * STAGE_SM)                // 73728 B

template <typename OutT>
__global__ __launch_bounds__(256, 2)
void gemm_fp16_kernel(const __half* __restrict__ A,
                      const __half* __restrict__ Bt,
                      const float* __restrict__ bias,
                      OutT* __restrict__ C,
                      int M, int N, int K)
{
    extern __shared__ char smem[];
    const uint32_t sbase = smem_u32(smem);
    const int tid = threadIdx.x;
    const int wid = tid >> 5, lane = tid & 31;
    const int blockRow = blockIdx.y * 128;
    const int blockCol = blockIdx.x * 128;
    const int m0 = (wid & 1) * 64;        // warp row origin
    const int n0 = (wid >> 1) * 32;       // warp col origin
    const int NC = K / 64;

    float acc[4][4][4];
    #pragma unroll
    for (int mt = 0; mt < 4; mt++)
        #pragma unroll
        for (int nt = 0; nt < 4; nt++)
            #pragma unroll
            for (int i = 0; i < 4; i++) acc[mt][nt][i] = 0.f;

    auto load_stage = [&](int stage, int k0) {
        const uint32_t st = sbase + stage * STAGE_SM;
        #pragma unroll
        for (int i = 0; i < 4; i++) {
            int cid = tid + i * 256;            // 0..1023
            int row = cid >> 3, c = cid & 7;
            CP16(st + row * ROW_STRIDE + c * 16,
                 A + (size_t)(blockRow + row) * K + k0 + c * 8);
            CP16(st + TILE_SM + row * ROW_STRIDE + c * 16,
                 Bt + (size_t)(blockCol + row) * K + k0 + c * 8);
        }
    };

    const uint32_t a_row = (lane & 15);
    const uint32_t a_cb  = (lane >> 4) * 16;
    const uint32_t b_n   = (lane & 7) | ((lane & 16) >> 1);
    const uint32_t b_kb  = ((lane >> 3) & 1) * 16;

    uint32_t bf[2][4][2];
    auto ld_bfrags = [&](int buf, uint32_t st, int k16) {
        #pragma unroll
        for (int j = 0; j < 2; j++) {
            uint32_t baddr = st + TILE_SM
                           + (n0 + j * 16 + b_n) * ROW_STRIDE
                           + k16 * 32 + b_kb;
            LDSM4(bf[buf][2 * j][0], bf[buf][2 * j][1],
                  bf[buf][2 * j + 1][0], bf[buf][2 * j + 1][1], baddr);
        }
    };

    load_stage(0, 0);
    CP_COMMIT();

    int p = 0;
    for (int kc = 0; kc < NC; kc++) {
        if (kc + 1 < NC) load_stage(1 - p, (kc + 1) * 64);
        CP_COMMIT();
        CP_WAITG1();
        __syncthreads();

        const uint32_t st = sbase + p * STAGE_SM;
        ld_bfrags(0, st, 0);
        #pragma unroll
        for (int k16 = 0; k16 < 4; k16++) {
            const int cur = k16 & 1;
            if (k16 < 3) ld_bfrags(cur ^ 1, st, k16 + 1);
            #pragma unroll
            for (int mt = 0; mt < 4; mt++) {
                uint32_t aaddr = st + (m0 + mt * 16 + a_row) * ROW_STRIDE
                               + k16 * 32 + a_cb;
                uint32_t a0, a1, a2, a3;
                LDSM4(a0, a1, a2, a3, aaddr);
                #pragma unroll
                for (int nt = 0; nt < 4; nt++)
                    mma16816(acc[mt][nt], a0, a1, a2, a3,
                             bf[cur][nt][0], bf[cur][nt][1]);
            }
        }
        __syncthreads();
        p ^= 1;
    }

    const int g = lane >> 2, t4 = lane & 3;
    #pragma unroll
    for (int mt = 0; mt < 4; mt++) {
        #pragma unroll
        for (int nt = 0; nt < 4; nt++) {
            int col = blockCol + n0 + nt * 8 + 2 * t4;
            float2 b2 = *(const float2*)(bias + col);
            int r0 = blockRow + m0 + mt * 16 + g;
            float v00 = acc[mt][nt][0] + b2.x, v01 = acc[mt][nt][1] + b2.y;
            float v10 = acc[mt][nt][2] + b2.x, v11 = acc[mt][nt][3] + b2.y;
            if constexpr (sizeof(OutT) == 2) {
                *(__half2*)((__half*)C + (size_t)r0 * N + col) =
                    __halves2half2(__float2half(v00), __float2half(v01));
                *(__half2*)((__half*)C + (size_t)(r0 + 8) * N + col) =
                    __halves2half2(__float2half(v10), __float2half(v11));
            } else {
                *(float2*)((float*)C + (size_t)r0 * N + col) = make_float2(v00, v01);
                *(float2*)((float*)C + (size_t)(r0 + 8) * N + col) = make_float2(v10, v11);
            }
        }
    }
}

// ---------------------------------------------------------------------------
// fp32 -> fp16 convert (elementwise)
// ---------------------------------------------------------------------------
__global__ void convert_kernel(const float* __restrict__ src,
                               __half* __restrict__ dst, size_t n4)
{
    size_t i = (size_t)blockIdx.x * blockDim.x + threadIdx.x;
    if (i >= n4) return;
    float4 v = ((const float4*)src)[i];
    __half2* dp = (__half2*)dst + i * 2;
    dp[0] = __halves2half2(__float2half(v.x), __float2half(v.y));
    dp[1] = __halves2half2(__float2half(v.z), __float2half(v.w));
}

// ---------------------------------------------------------------------------
// fp32 [R,C] -> transposed fp16 [C,R]
// ---------------------------------------------------------------------------
__global__ void transpose_h_kernel(const float* __restrict__ src,
                                   __half* __restrict__ dst, int R, int C)
{
    __shared__ float tile[32][33];
    int tx = threadIdx.x, ty = threadIdx.y;     // (32, 8)
    int c0 = blockIdx.x * 32, r0 = blockIdx.y * 32;
    #pragma unroll
    for (int j = 0; j < 32; j += 8)
        tile[ty + j][tx] = src[(size_t)(r0 + ty + j) * C + c0 + tx];
    __syncthreads();
    #pragma unroll
    for (int j = 0; j < 32; j += 8)
        dst[(size_t)(c0 + ty + j) * R + r0 + tx] = __float2half(tile[tx][ty + j]);
}

// ---------------------------------------------------------------------------
// Scan phase A + B (NSEG=128, SEGLEN=32)
// ---------------------------------------------------------------------------
__global__ void scan_phaseA_kernel()
{
    int id = blockIdx.x * blockDim.x + threadIdx.x;
    if (id >= BATCH * NSEG * D_MODEL) return;
    int c = id % D_MODEL;
    int seg = (id / D_MODEL) % NSEG;
    int b = id / (D_MODEL * NSEG);
    const __half* base = g_u16 + (size_t)(b * SEQ_L + seg * SEGLEN) * N1;
    float A = 1.f, Bc = 0.f;
    for (int i = 0; i < SEGLEN; i++) {
        float fl = __half2float(base[(size_t)i * N1 + 2 * D_MODEL + c]);
        float v  = __half2float(base[(size_t)i * N1 + c]);
        float f = 1.f / (1.f + __expf(-fl));
        A = f * A;
        Bc = f * Bc + (1.f - f) * v;
    }
    int idx = seg * NSEQ + b * D_MODEL + c;
    g_segA[idx] = A;
    g_segB[idx] = Bc;
}

__global__ void scan_phaseB_kernel()
{
    int id = blockIdx.x * blockDim.x + threadIdx.x;
    if (id >= NSEQ) return;
    float h = 0.f;
    #pragma unroll 8
    for (int s = 0; s < NSEG; s++) {
        g_carry[s * NSEQ + id] = h;
        h = g_segA[s * NSEQ + id] * h + g_segB[s * NSEQ + id];
    }
}

// ---------------------------------------------------------------------------
// FUSED phase C + LayerNorm + fp16 A2 conversion (v2):
//  - software-pipelined u loads (next step's LDGs issued before this step's
//    reduction barrier)
//  - ONE barrier per step: warp partials -> smem -> every warp redundantly
//    reduces the 32 partials (double-buffered smem)
// One 1024-thread block per (b, seg); thread c owns channel c; 32 steps.
// ---------------------------------------------------------------------------
__global__ __launch_bounds__(1024)
void scan_ln_fused_kernel(const float* __restrict__ gamma,
                          const float* __restrict__ beta)
{
    const int c = threadIdx.x;              // channel 0..1023
    const int seg = blockIdx.x % NSEG;
    const int b = blockIdx.x / NSEG;
    const int wid = c >> 5, lane = c & 31;

    __shared__ float shs[2][32], shq[2][32];

    const __half* base = g_u16 + (size_t)(b * SEQ_L + seg * SEGLEN) * N1;
    __half* aout = g_A2 + (size_t)(b * SEQ_L + seg * SEGLEN) * D_MODEL + c;

    float h = g_carry[seg * NSEQ + b * D_MODEL + c];
    const float gmv = gamma[c], btv = beta[c];

    // prime step-0 inputs
    __half cfl = base[2 * D_MODEL + c];
    __half cv  = base[c];
    __half co  = base[D_MODEL + c];

    for (int i = 0; i < SEGLEN; i++) {
        // issue next step's loads BEFORE the barrier (latency hides under reduce)
        __half nfl, nv, no;
        if (i + 1 < SEGLEN) {
            const __half* nb = base + (size_t)(i + 1) * N1;
            nfl = nb[2 * D_MODEL + c];
            nv  = nb[c];
            no  = nb[D_MODEL + c];
        }

        float fl = __half2float(cfl), v = __half2float(cv), o = __half2float(co);
        float f = 1.f / (1.f + __expf(-fl));
        h = f * h + (1.f - f) * v;
        float gt = h * (o / (1.f + __expf(-o)));   // gate output

        // warp-level partial sums
        float s = gt, sq = gt * gt;
        #pragma unroll
        for (int off = 16; off > 0; off >>= 1) {
            s  += __shfl_xor_sync(0xffffffffu, s, off);
            sq += __shfl_xor_sync(0xffffffffu, sq, off);
        }
        const int buf = i & 1;
        if (lane == 0) { shs[buf][wid] = s; shq[buf][wid] = sq; }
        __syncthreads();                       // ONE barrier per step
        // every warp redundantly reduces the 32 partials
        float s2 = shs[buf][lane], q2 = shq[buf][lane];
        #pragma unroll
        for (int off = 16; off > 0; off >>= 1) {
            s2 += __shfl_xor_sync(0xffffffffu, s2, off);
            q2 += __shfl_xor_sync(0xffffffffu, q2, off);
        }
        const float mu = s2 * (1.f / D_MODEL);
        const float var = q2 * (1.f / D_MODEL) - mu * mu;
        const float rstd = rsqrtf(var + LN_EPS);

        aout[(size_t)i * D_MODEL] = __float2half((gt - mu) * rstd * gmv + btv);

        cfl = nfl; cv = nv; co = no;
    }
}

// ---------------------------------------------------------------------------
// Launch
// ---------------------------------------------------------------------------
extern "C" void kernel_launch(void* const* d_in, const int* in_sizes, int n_in,
                              void* d_out, int out_size)
{
    const float* x     = (const float*)d_in[0];
    const float* W_in  = (const float*)d_in[1];
    const float* b_in  = (const float*)d_in[2];
    const float* gamma = (const float*)d_in[3];
    const float* beta  = (const float*)d_in[4];
    const float* W_out = (const float*)d_in[5];
    const float* b_out = (const float*)d_in[6];
    float* out = (float*)d_out;

    __half *u16, *a1, *b1t, *a2, *b2t;
    cudaGetSymbolAddress((void**)&u16, g_u16);
    cudaGetSymbolAddress((void**)&a1, g_A1);
    cudaGetSymbolAddress((void**)&b1t, g_B1t);
    cudaGetSymbolAddress((void**)&a2, g_A2);
    cudaGetSymbolAddress((void**)&b2t, g_B2t);

    cudaFuncSetAttribute(gemm_fp16_kernel<__half>,
                         cudaFuncAttributeMaxDynamicSharedMemorySize, GEMM_SMEM);
    cudaFuncSetAttribute(gemm_fp16_kernel<float>,
                         cudaFuncAttributeMaxDynamicSharedMemorySize, GEMM_SMEM);

    // 0) operand conversion
    {
        size_t n4 = (size_t)M_TOK * D_MODEL / 4;
        convert_kernel<<<(unsigned)((n4 + 255) / 256), 256>>>(x, a1, n4);
        dim3 blk(32, 8);
        transpose_h_kernel<<<dim3(N1 / 32, D_MODEL / 32), blk>>>(W_in, b1t, D_MODEL, N1);
        transpose_h_kernel<<<dim3(D_MODEL / 32, D_MODEL / 32), blk>>>(W_out, b2t, D_MODEL, D_MODEL);
    }

    // 1) u = x @ W_in + b_in   [16384, 3072] (fp16 output)
    gemm_fp16_kernel<__half><<<dim3(N1 / 128, M_TOK / 128), 256, GEMM_SMEM>>>(
        a1, b1t, b_in, u16, M_TOK, N1, D_MODEL);

    // 2-3) scan segment maps + carries
    {
        int total = BATCH * NSEG * D_MODEL;
        scan_phaseA_kernel<<<total / 256, 256>>>();
        scan_phaseB_kernel<<<NSEQ / 256, 256>>>();
    }

    // 4) fused scan replay + SiLU gate + LayerNorm -> fp16 A2
    scan_ln_fused_kernel<<<BATCH * NSEG, 1024>>>(gamma, beta);

    // 5) out = y @ W_out + b_out  [16384, 1024] (fp32 output)
    gemm_fp16_kernel<float><<<dim3(D_MODEL / 128, M_TOK / 128), 256, GEMM_SMEM>>>(
        a2, b2t, b_out, out, M_TOK, D_MODEL, D_MODEL);
}

// round 15
// speedup vs baseline: 1.0524x; 1.0524x over previous
#include <cuda_runtime.h>
#include <cuda_fp16.h>
#include <math.h>
#include <cstdint>

// Problem constants
#define D_MODEL 1024
#define SEQ_L   4096
#define BATCH   4
#define M_TOK   (BATCH * SEQ_L)     // 16384 tokens
#define N1      (3 * D_MODEL)       // 3072
#define NSEG    64
#define SEGLEN  (SEQ_L / NSEG)      // 64
#define NSEQ    (BATCH * D_MODEL)   // 4096 scan sequences
#define LN_EPS  1e-5f

// ---------------------------------------------------------------------------
// Scratch (static device arrays, allocation-free)
// ---------------------------------------------------------------------------
__device__ __half g_u16[(size_t)M_TOK * N1];      // 96 MB: u (fp16)
__device__ __half g_g16[(size_t)M_TOK * D_MODEL]; // 32 MB: scan/gate output (fp16)
__device__ float g_segA[NSEG * NSEQ];
__device__ float g_segB[NSEG * NSEQ];
__device__ float g_carry[NSEG * NSEQ];

// fp16 operands (plain fp16 A, B transposed [N,K])
__device__ __half g_A1[(size_t)M_TOK * D_MODEL];
__device__ __half g_B1t[(size_t)N1 * D_MODEL];
__device__ __half g_A2[(size_t)M_TOK * D_MODEL];
__device__ __half g_B2t[(size_t)D_MODEL * D_MODEL];

// ---------------------------------------------------------------------------
// PTX helpers (base sm_100-legal: cp.async, ldmatrix, mma.sync)
// ---------------------------------------------------------------------------
__device__ __forceinline__ uint32_t smem_u32(const void* p) {
    uint32_t a;
    asm("{ .reg .u64 t; cvta.to.shared.u64 t, %1; cvt.u32.u64 %0, t; }" : "=r"(a) : "l"(p));
    return a;
}
#define CP16(smem_addr, gptr) \
    asm volatile("cp.async.cg.shared.global [%0], [%1], 16;" :: "r"(smem_addr), "l"(gptr))
#define CP_COMMIT() asm volatile("cp.async.commit_group;" ::: "memory")
#define CP_WAITG1() asm volatile("cp.async.wait_group 1;" ::: "memory")

#define LDSM4(r0, r1, r2, r3, addr) \
    asm volatile("ldmatrix.sync.aligned.m8n8.x4.shared.b16 {%0,%1,%2,%3}, [%4];" \
                 : "=r"(r0), "=r"(r1), "=r"(r2), "=r"(r3) : "r"(addr))

__device__ __forceinline__ void mma16816(float* c, uint32_t a0, uint32_t a1,
                                         uint32_t a2, uint32_t a3,
                                         uint32_t b0, uint32_t b1) {
    asm volatile(
        "mma.sync.aligned.m16n8k16.row.col.f32.f16.f16.f32 "
        "{%0,%1,%2,%3}, {%4,%5,%6,%7}, {%8,%9}, {%0,%1,%2,%3};"
        : "+f"(c[0]), "+f"(c[1]), "+f"(c[2]), "+f"(c[3])
        : "r"(a0), "r"(a1), "r"(a2), "r"(a3), "r"(b0), "r"(b1));
}

// ---------------------------------------------------------------------------
// fp16 GEMM (R11-exact): C[M,N] = A[M,K] @ Bt[N,K]^T + bias
// CTA 128x128, BK=64, 256 threads = 8 warps of 64x32, 2-stage cp.async,
// B-fragment double-buffering across k16 steps.
// ---------------------------------------------------------------------------
#define ROW_STRIDE 144
#define TILE_SM (128 * ROW_STRIDE)              // 18432 B
#define STAGE_SM (2 * TILE_SM)                  // 36864 B (A + B)
#define GEMM_SMEM (2 * STAGE_SM)                // 73728 B

template <typename OutT>
__global__ __launch_bounds__(256, 2)
void gemm_fp16_kernel(const __half* __restrict__ A,
                      const __half* __restrict__ Bt,
                      const float* __restrict__ bias,
                      OutT* __restrict__ C,
                      int M, int N, int K)
{
    extern __shared__ char smem[];
    const uint32_t sbase = smem_u32(smem);
    const int tid = threadIdx.x;
    const int wid = tid >> 5, lane = tid & 31;
    const int blockRow = blockIdx.y * 128;
    const int blockCol = blockIdx.x * 128;
    const int m0 = (wid & 1) * 64;        // warp row origin
    const int n0 = (wid >> 1) * 32;       // warp col origin
    const int NC = K / 64;

    float acc[4][4][4];
    #pragma unroll
    for (int mt = 0; mt < 4; mt++)
        #pragma unroll
        for (int nt = 0; nt < 4; nt++)
            #pragma unroll
            for (int i = 0; i < 4; i++) acc[mt][nt][i] = 0.f;

    auto load_stage = [&](int stage, int k0) {
        const uint32_t st = sbase + stage * STAGE_SM;
        #pragma unroll
        for (int i = 0; i < 4; i++) {
            int cid = tid + i * 256;            // 0..1023
            int row = cid >> 3, c = cid & 7;
            CP16(st + row * ROW_STRIDE + c * 16,
                 A + (size_t)(blockRow + row) * K + k0 + c * 8);
            CP16(st + TILE_SM + row * ROW_STRIDE + c * 16,
                 Bt + (size_t)(blockCol + row) * K + k0 + c * 8);
        }
    };

    const uint32_t a_row = (lane & 15);
    const uint32_t a_cb  = (lane >> 4) * 16;
    const uint32_t b_n   = (lane & 7) | ((lane & 16) >> 1);
    const uint32_t b_kb  = ((lane >> 3) & 1) * 16;

    uint32_t bf[2][4][2];
    auto ld_bfrags = [&](int buf, uint32_t st, int k16) {
        #pragma unroll
        for (int j = 0; j < 2; j++) {
            uint32_t baddr = st + TILE_SM
                           + (n0 + j * 16 + b_n) * ROW_STRIDE
                           + k16 * 32 + b_kb;
            LDSM4(bf[buf][2 * j][0], bf[buf][2 * j][1],
                  bf[buf][2 * j + 1][0], bf[buf][2 * j + 1][1], baddr);
        }
    };

    load_stage(0, 0);
    CP_COMMIT();

    int p = 0;
    for (int kc = 0; kc < NC; kc++) {
        if (kc + 1 < NC) load_stage(1 - p, (kc + 1) * 64);
        CP_COMMIT();
        CP_WAITG1();
        __syncthreads();

        const uint32_t st = sbase + p * STAGE_SM;
        ld_bfrags(0, st, 0);
        #pragma unroll
        for (int k16 = 0; k16 < 4; k16++) {
            const int cur = k16 & 1;
            if (k16 < 3) ld_bfrags(cur ^ 1, st, k16 + 1);
            #pragma unroll
            for (int mt = 0; mt < 4; mt++) {
                uint32_t aaddr = st + (m0 + mt * 16 + a_row) * ROW_STRIDE
                               + k16 * 32 + a_cb;
                uint32_t a0, a1, a2, a3;
                LDSM4(a0, a1, a2, a3, aaddr);
                #pragma unroll
                for (int nt = 0; nt < 4; nt++)
                    mma16816(acc[mt][nt], a0, a1, a2, a3,
                             bf[cur][nt][0], bf[cur][nt][1]);
            }
        }
        __syncthreads();
        p ^= 1;
    }

    const int g = lane >> 2, t4 = lane & 3;
    #pragma unroll
    for (int mt = 0; mt < 4; mt++) {
        #pragma unroll
        for (int nt = 0; nt < 4; nt++) {
            int col = blockCol + n0 + nt * 8 + 2 * t4;
            float2 b2 = *(const float2*)(bias + col);
            int r0 = blockRow + m0 + mt * 16 + g;
            float v00 = acc[mt][nt][0] + b2.x, v01 = acc[mt][nt][1] + b2.y;
            float v10 = acc[mt][nt][2] + b2.x, v11 = acc[mt][nt][3] + b2.y;
            if constexpr (sizeof(OutT) == 2) {
                *(__half2*)((__half*)C + (size_t)r0 * N + col) =
                    __halves2half2(__float2half(v00), __float2half(v01));
                *(__half2*)((__half*)C + (size_t)(r0 + 8) * N + col) =
                    __halves2half2(__float2half(v10), __float2half(v11));
            } else {
                *(float2*)((float*)C + (size_t)r0 * N + col) = make_float2(v00, v01);
                *(float2*)((float*)C + (size_t)(r0 + 8) * N + col) = make_float2(v10, v11);
            }
        }
    }
}

// ---------------------------------------------------------------------------
// fp32 -> fp16 convert (elementwise)
// ---------------------------------------------------------------------------
__global__ void convert_kernel(const float* __restrict__ src,
                               __half* __restrict__ dst, size_t n4)
{
    size_t i = (size_t)blockIdx.x * blockDim.x + threadIdx.x;
    if (i >= n4) return;
    float4 v = ((const float4*)src)[i];
    __half2* dp = (__half2*)dst + i * 2;
    dp[0] = __halves2half2(__float2half(v.x), __float2half(v.y));
    dp[1] = __halves2half2(__float2half(v.z), __float2half(v.w));
}

// ---------------------------------------------------------------------------
// fp32 [R,C] -> transposed fp16 [C,R]
// ---------------------------------------------------------------------------
__global__ void transpose_h_kernel(const float* __restrict__ src,
                                   __half* __restrict__ dst, int R, int C)
{
    __shared__ float tile[32][33];
    int tx = threadIdx.x, ty = threadIdx.y;     // (32, 8)
    int c0 = blockIdx.x * 32, r0 = blockIdx.y * 32;
    #pragma unroll
    for (int j = 0; j < 32; j += 8)
        tile[ty + j][tx] = src[(size_t)(r0 + ty + j) * C + c0 + tx];
    __syncthreads();
    #pragma unroll
    for (int j = 0; j < 32; j += 8)
        dst[(size_t)(c0 + ty + j) * R + r0 + tx] = __float2half(tile[tx][ty + j]);
}

// ---------------------------------------------------------------------------
// Segmented gated scan (3 phases, scalar, fp16 u — R11-exact loops)
// ---------------------------------------------------------------------------
__global__ void scan_phaseA_kernel()
{
    int id = blockIdx.x * blockDim.x + threadIdx.x;
    if (id >= BATCH * NSEG * D_MODEL) return;
    int c = id % D_MODEL;
    int seg = (id / D_MODEL) % NSEG;
    int b = id / (D_MODEL * NSEG);
    const __half* base = g_u16 + (size_t)(b * SEQ_L + seg * SEGLEN) * N1;
    float A = 1.f, Bc = 0.f;
    for (int i = 0; i < SEGLEN; i++) {
        float fl = __half2float(base[(size_t)i * N1 + 2 * D_MODEL + c]);
        float v  = __half2float(base[(size_t)i * N1 + c]);
        float f = 1.f / (1.f + __expf(-fl));
        A = f * A;
        Bc = f * Bc + (1.f - f) * v;
    }
    int idx = seg * NSEQ + b * D_MODEL + c;
    g_segA[idx] = A;
    g_segB[idx] = Bc;
}

__global__ void scan_phaseB_kernel()
{
    int id = blockIdx.x * blockDim.x + threadIdx.x;
    if (id >= NSEQ) return;
    float h = 0.f;
    #pragma unroll 8
    for (int s = 0; s < NSEG; s++) {
        g_carry[s * NSEQ + id] = h;
        h = g_segA[s * NSEQ + id] * h + g_segB[s * NSEQ + id];
    }
}

__global__ void scan_phaseC_kernel()
{
    int id = blockIdx.x * blockDim.x + threadIdx.x;
    if (id >= BATCH * NSEG * D_MODEL) return;
    int c = id % D_MODEL;
    int seg = (id / D_MODEL) % NSEG;
    int b = id / (D_MODEL * NSEG);
    const __half* base = g_u16 + (size_t)(b * SEQ_L + seg * SEGLEN) * N1;
    __half* gout = g_g16 + (size_t)(b * SEQ_L + seg * SEGLEN) * D_MODEL + c;
    float h = g_carry[seg * NSEQ + b * D_MODEL + c];
    for (int i = 0; i < SEGLEN; i++) {
        float fl = __half2float(base[(size_t)i * N1 + 2 * D_MODEL + c]);
        float v  = __half2float(base[(size_t)i * N1 + c]);
        float o  = __half2float(base[(size_t)i * N1 + D_MODEL + c]);
        float f = 1.f / (1.f + __expf(-fl));
        h = f * h + (1.f - f) * v;
        float silu = o / (1.f + __expf(-o));
        gout[(size_t)i * D_MODEL] = __float2half(h * silu);
    }
}

// ---------------------------------------------------------------------------
// LayerNorm on fp16 g -> fp16 A2 operand (fused conversion)
// ---------------------------------------------------------------------------
__device__ __forceinline__ float block_reduce_sum_256(float v)
{
    __shared__ float shm[8];
    int lane = threadIdx.x & 31;
    #pragma unroll
    for (int o = 16; o > 0; o >>= 1) v += __shfl_xor_sync(0xffffffffu, v, o);
    __syncthreads();
    if (lane == 0) shm[threadIdx.x >> 5] = v;
    __syncthreads();
    float r = (lane < 8) ? shm[lane] : 0.f;
    #pragma unroll
    for (int o = 4; o > 0; o >>= 1) r += __shfl_xor_sync(0xffffffffu, r, o);
    return __shfl_sync(0xffffffffu, r, 0);
}

__global__ __launch_bounds__(256)
void layernorm_h_kernel(const float* __restrict__ gamma, const float* __restrict__ beta)
{
    const int row = blockIdx.x;
    const __half2* p2 = (const __half2*)(g_g16 + (size_t)row * D_MODEL);
    const int tid = threadIdx.x;

    __half2 ha = p2[tid * 2], hb = p2[tid * 2 + 1];
    float2 fa = __half22float2(ha), fb = __half22float2(hb);
    float s = fa.x + fa.y + fb.x + fb.y;
    s = block_reduce_sum_256(s);
    const float mu = s * (1.f / D_MODEL);

    float d0 = fa.x - mu, d1 = fa.y - mu, d2 = fb.x - mu, d3 = fb.y - mu;
    float sq = d0 * d0 + d1 * d1 + d2 * d2 + d3 * d3;
    sq = block_reduce_sum_256(sq);
    const float rstd = rsqrtf(sq * (1.f / D_MODEL) + LN_EPS);

    float4 gm = ((const float4*)gamma)[tid];
    float4 bt = ((const float4*)beta)[tid];
    float y0 = d0 * rstd * gm.x + bt.x;
    float y1 = d1 * rstd * gm.y + bt.y;
    float y2 = d2 * rstd * gm.z + bt.z;
    float y3 = d3 * rstd * gm.w + bt.w;

    size_t base = (size_t)row * D_MODEL + tid * 4;
    __half2* hp = (__half2*)(g_A2 + base);
    hp[0] = __halves2half2(__float2half(y0), __float2half(y1));
    hp[1] = __halves2half2(__float2half(y2), __float2half(y3));
}

// ---------------------------------------------------------------------------
// Launch
// ---------------------------------------------------------------------------
extern "C" void kernel_launch(void* const* d_in, const int* in_sizes, int n_in,
                              void* d_out, int out_size)
{
    const float* x     = (const float*)d_in[0];
    const float* W_in  = (const float*)d_in[1];
    const float* b_in  = (const float*)d_in[2];
    const float* gamma = (const float*)d_in[3];
    const float* beta  = (const float*)d_in[4];
    const float* W_out = (const float*)d_in[5];
    const float* b_out = (const float*)d_in[6];
    float* out = (float*)d_out;

    __half *u16, *a1, *b1t, *a2, *b2t;
    cudaGetSymbolAddress((void**)&u16, g_u16);
    cudaGetSymbolAddress((void**)&a1, g_A1);
    cudaGetSymbolAddress((void**)&b1t, g_B1t);
    cudaGetSymbolAddress((void**)&a2, g_A2);
    cudaGetSymbolAddress((void**)&b2t, g_B2t);

    cudaFuncSetAttribute(gemm_fp16_kernel<__half>,
                         cudaFuncAttributeMaxDynamicSharedMemorySize, GEMM_SMEM);
    cudaFuncSetAttribute(gemm_fp16_kernel<float>,
                         cudaFuncAttributeMaxDynamicSharedMemorySize, GEMM_SMEM);

    // 0) operand conversion
    {
        size_t n4 = (size_t)M_TOK * D_MODEL / 4;
        convert_kernel<<<(unsigned)((n4 + 255) / 256), 256>>>(x, a1, n4);
        dim3 blk(32, 8);
        transpose_h_kernel<<<dim3(N1 / 32, D_MODEL / 32), blk>>>(W_in, b1t, D_MODEL, N1);
        transpose_h_kernel<<<dim3(D_MODEL / 32, D_MODEL / 32), blk>>>(W_out, b2t, D_MODEL, D_MODEL);
    }

    // 1) u = x @ W_in + b_in   [16384, 3072] (fp16 output)
    gemm_fp16_kernel<__half><<<dim3(N1 / 128, M_TOK / 128), 256, GEMM_SMEM>>>(
        a1, b1t, b_in, u16, M_TOK, N1, D_MODEL);

    // 2-4) segmented gated scan (fp16 u, fp16 g)
    {
        int total = BATCH * NSEG * D_MODEL;
        scan_phaseA_kernel<<<total / 256, 256>>>();
        scan_phaseB_kernel<<<NSEQ / 256, 256>>>();
        scan_phaseC_kernel<<<total / 256, 256>>>();
    }

    // 5) LayerNorm (fp16 in) -> A2 fp16
    layernorm_h_kernel<<<M_TOK, 256>>>(gamma, beta);

    // 6) out = y @ W_out + b_out  [16384, 1024] (fp32 output)
    gemm_fp16_kernel<float><<<dim3(D_MODEL / 128, M_TOK / 128), 256, GEMM_SMEM>>>(
        a2, b2t, b_out, out, M_TOK, D_MODEL, D_MODEL);
}